// round 11
// baseline (speedup 1.0000x reference)
#include <cuda_runtime.h>

// Leapfrog (KDK), softened point mass: a = -q / (r*(r+1)^2 + 1e-12).
//
// v11 = v7 (scalar 2N threads, block=64/2048 CTAs, full unroll, rsqrt for 1/r)
// with the kick coefficient folded into the denominator BEFORE the reciprocal:
//   i_c = 1/|coef| precomputed (one IEEE div in the prologue; coef = dt^2 or
//   dt^2/2 after momentum scaling P = dt*p)
//   d2  = den * i_c;   scm = rcp.approx(d2)  // = |coef|/den
//   P  -= scm * q  via FREE operand negation in FFMA
// Deletes den*den and the sc=inv*ncoef mul: 15 issue-slots/step (was 16) and
// 68-cycle step path (was 72) — a strict improvement under both the
// slot-throughput and latency models. Diagnostic: if rcp.approx emits ALU
// companions (R9 ambiguity), alu% jumps >16 and this is flat.
//
// Inputs: d_in[0]=ts f32[N], d_in[1]=w0_lead f32[N,6], d_in[2]=w0_trail f32[N,6],
//         d_in[3]=n_steps i32. Output f32[2N,6]: row 2i=trail_i, 2i+1=lead_i.

__device__ __forceinline__ float rsqrt_ap(float x) {
    float r; asm("rsqrt.approx.f32 %0, %1;" : "=f"(r) : "f"(x)); return r;
}
__device__ __forceinline__ float rcp_ap(float x) {
    float r; asm("rcp.approx.f32 %0, %1;" : "=f"(r) : "f"(x)); return r;
}

// P -= (|coef|/den) * q, with i_c = 1/|coef| folded into den.
// 10 fma-class ops + 2 MUFU per call.
__device__ __forceinline__ void kick(float& qx, float& qy, float& qz,
                                     float& Px, float& Py, float& Pz,
                                     float i_c) {
    float r2  = fmaf(qx, qx, fmaf(qy, qy, qz * qz));
    float u   = rsqrt_ap(r2);            // 1/r
    float r   = r2 * u;                  // r
    float t   = fmaf(r, r2, r);          // r*r2 + r
    float den = fmaf(2.0f, r2, t);       // r(1+r)^2  (imm multiplier)
    float d2  = den * i_c;               // den/|coef|
    float scm = rcp_ap(d2);              // |coef|/den  (> 0)
    Px = fmaf(-scm, qx, Px);             // neg via operand modifier (free)
    Py = fmaf(-scm, qy, Py);
    Pz = fmaf(-scm, qz, Pz);
}

template <int INTERIOR, bool FULL_UNROLL>
__device__ __forceinline__ void integrate(float& qx, float& qy, float& qz,
                                          float& Px, float& Py, float& Pz,
                                          float i_full, float i_half,
                                          int interior_rt) {
    kick(qx, qy, qz, Px, Py, Pz, i_half);
    if (FULL_UNROLL) {
        #pragma unroll
        for (int s = 0; s < INTERIOR; ++s) {
            qx += Px; qy += Py; qz += Pz;           // drift (P = dt*p)
            kick(qx, qy, qz, Px, Py, Pz, i_full);
        }
    } else {
        #pragma unroll 4
        for (int s = 0; s < interior_rt; ++s) {
            qx += Px; qy += Py; qz += Pz;
            kick(qx, qy, qz, Px, Py, Pz, i_full);
        }
    }
    qx += Px; qy += Py; qz += Pz;
    kick(qx, qy, qz, Px, Py, Pz, i_half);
}

__global__ void __launch_bounds__(64)
leapfrog_v11_kernel(const float* __restrict__ ts,
                    const float* __restrict__ w0_lead,
                    const float* __restrict__ w0_trail,
                    const int*   __restrict__ n_steps_ptr,
                    float* __restrict__ out,
                    int N) {
    int tid = blockIdx.x * blockDim.x + threadIdx.x;
    if (tid >= 2 * N) return;

    int b = (tid >= N) ? 1 : 0;        // 0 = trail, 1 = lead
    int i = tid - b * N;

    const float* __restrict__ w0 = b ? w0_lead : w0_trail;

    int n_steps = *n_steps_ptr;
    float t_f = ts[N - 1] + 0.001f;    // broadcast, L2-resident

    const float2* __restrict__ row = reinterpret_cast<const float2*>(w0 + 6 * i);
    float2 v0 = row[0];
    float2 v1 = row[1];
    float2 v2 = row[2];
    float qx = v0.x, qy = v0.y, qz = v1.x;
    float px = v1.y, py = v2.x, pz = v2.y;

    float dt, i_full;
    if (n_steps == 64) {
        float x = t_f - ts[i];                  // > 0 (>= 0.001)
        dt = x * 0.015625f;                     // exact /64
        i_full = 4096.0f / (x * x);             // 1/dt^2, one IEEE div
    } else {
        dt = (t_f - ts[i]) / (float)n_steps;
        i_full = 1.0f / (dt * dt);
    }
    float i_half = i_full + i_full;             // 1/(dt^2/2)

    // Momentum scaling: P = dt * p  =>  drift is q += P; kick coef = dt^2 (/2).
    float Px = dt * px, Py = dt * py, Pz = dt * pz;

    if (n_steps == 64) {
        integrate<63, true>(qx, qy, qz, Px, Py, Pz, i_full, i_half, 63);
    } else {
        integrate<0, false>(qx, qy, qz, Px, Py, Pz, i_full, i_half, n_steps - 1);
    }

    // Recover p = P / dt (outside the hot loop).
    float inv_dt = 1.0f / dt;
    px = Px * inv_dt; py = Py * inv_dt; pz = Pz * inv_dt;

    int orow = 2 * i + b;
    float2* __restrict__ orow_p = reinterpret_cast<float2*>(out + 6 * orow);
    orow_p[0] = make_float2(qx, qy);
    orow_p[1] = make_float2(qz, px);
    orow_p[2] = make_float2(py, pz);
}

extern "C" void kernel_launch(void* const* d_in, const int* in_sizes, int n_in,
                              void* d_out, int out_size) {
    const float* ts       = (const float*)d_in[0];
    const float* w0_lead  = (const float*)d_in[1];
    const float* w0_trail = (const float*)d_in[2];
    const int*   n_steps  = (const int*)d_in[3];
    float* out = (float*)d_out;

    int N = in_sizes[0];
    int total = 2 * N;
    int threads = 64;                   // 2048 CTAs -> balanced 13-14 per SM
    int blocks = (total + threads - 1) / threads;
    leapfrog_v11_kernel<<<blocks, threads>>>(ts, w0_lead, w0_trail, n_steps, out, N);
}

// round 12
// speedup vs baseline: 1.1597x; 1.1597x over previous
#include <cuda_runtime.h>

// Leapfrog (KDK), softened point mass: a = -q / (r*(r+1)^2 + 1e-12).
//
// v12 = v7 shape (scalar 2N threads, block=64/2048 CTAs, full unroll) with
// MUFU halved: 1/(1+r) maintained as loop-carried g via 2 Newton iterations
// (seed = previous step's g; rel seed error <= |dq_step| since 1+r >= 1, so
// two iterations give ~e^4 <= 1e-6 typical). 1/den = u * g^2 exactly, with
// u = rsqrt(r2) the ONLY MUFU per interior step (was 2). All 11 prior rounds
// left MUFU untouched and converged to ~12us; this is the discriminating
// experiment for "MUFU is the hidden binder".
//
// Inputs: d_in[0]=ts f32[N], d_in[1]=w0_lead f32[N,6], d_in[2]=w0_trail f32[N,6],
//         d_in[3]=n_steps i32. Output f32[2N,6]: row 2i=trail_i, 2i+1=lead_i.

__device__ __forceinline__ float rsqrt_ap(float x) {
    float r; asm("rsqrt.approx.f32 %0, %1;" : "=f"(r) : "f"(x)); return r;
}

// Full-accuracy kick (2 MUFU), also (re)initializes g = 1/(1+r).
__device__ __forceinline__ void kick_init(float& qx, float& qy, float& qz,
                                          float& px, float& py, float& pz,
                                          float ncoef, float& g) {
    float r2 = fmaf(qx, qx, fmaf(qy, qy, qz * qz));
    float u  = rsqrt_ap(r2);            // 1/r
    float r  = r2 * u;                  // r
    float s  = 1.0f + r;
    g        = rsqrt_ap(s * s);         // 1/(1+r), exact-ish
    float sc = (ncoef * u) * (g * g);   // -coef * u * g^2 = -coef/den
    px = fmaf(sc, qx, px);
    py = fmaf(sc, qy, py);
    pz = fmaf(sc, qz, pz);
}

// Fast kick: 1 MUFU; g refreshed from last step's value by 2 Newton steps.
__device__ __forceinline__ void kick_fast(float& qx, float& qy, float& qz,
                                          float& px, float& py, float& pz,
                                          float ncoef, float& g) {
    float r2 = fmaf(qx, qx, fmaf(qy, qy, qz * qz));
    float u  = rsqrt_ap(r2);            // 1/r            (only MUFU)
    float r  = r2 * u;                  // r
    float s  = 1.0f + r;
    // Newton toward 1/s (seed: previous step's g; e' = e^2):
    float t0 = fmaf(-s, g, 2.0f);  g = g * t0;
    float t1 = fmaf(-s, g, 2.0f);  g = g * t1;
    float sc = (ncoef * u) * (g * g);   // -coef/(r(1+r)^2)
    px = fmaf(sc, qx, px);
    py = fmaf(sc, qy, py);
    pz = fmaf(sc, qz, pz);
}

__device__ __forceinline__ void drift(float& qx, float& qy, float& qz,
                                      float px, float py, float pz, float dt) {
    qx = fmaf(dt, px, qx);
    qy = fmaf(dt, py, qy);
    qz = fmaf(dt, pz, qz);
}

template <int INTERIOR, bool FULL_UNROLL>
__device__ __forceinline__ void integrate(float& qx, float& qy, float& qz,
                                          float& px, float& py, float& pz,
                                          float dt, int interior_rt) {
    float nhdt = -0.5f * dt;
    float ndt  = -dt;
    float g;

    kick_init(qx, qy, qz, px, py, pz, nhdt, g);   // also seeds g
    if (FULL_UNROLL) {
        #pragma unroll
        for (int s = 0; s < INTERIOR; ++s) {
            drift(qx, qy, qz, px, py, pz, dt);
            kick_fast(qx, qy, qz, px, py, pz, ndt, g);
        }
    } else {
        #pragma unroll 4
        for (int s = 0; s < interior_rt; ++s) {
            drift(qx, qy, qz, px, py, pz, dt);
            kick_fast(qx, qy, qz, px, py, pz, ndt, g);
        }
    }
    drift(qx, qy, qz, px, py, pz, dt);
    kick_fast(qx, qy, qz, px, py, pz, nhdt, g);
}

__global__ void __launch_bounds__(64)
leapfrog_v12_kernel(const float* __restrict__ ts,
                    const float* __restrict__ w0_lead,
                    const float* __restrict__ w0_trail,
                    const int*   __restrict__ n_steps_ptr,
                    float* __restrict__ out,
                    int N) {
    int tid = blockIdx.x * blockDim.x + threadIdx.x;
    if (tid >= 2 * N) return;

    int b = (tid >= N) ? 1 : 0;        // 0 = trail, 1 = lead
    int i = tid - b * N;

    const float* __restrict__ w0 = b ? w0_lead : w0_trail;

    int n_steps = *n_steps_ptr;
    float t_f = ts[N - 1] + 0.001f;    // broadcast, L2-resident

    const float2* __restrict__ row = reinterpret_cast<const float2*>(w0 + 6 * i);
    float2 v0 = row[0];
    float2 v1 = row[1];
    float2 v2 = row[2];
    float qx = v0.x, qy = v0.y, qz = v1.x;
    float px = v1.y, py = v2.x, pz = v2.y;

    if (n_steps == 64) {
        float dt = (t_f - ts[i]) * 0.015625f;   // exact /64
        integrate<63, true>(qx, qy, qz, px, py, pz, dt, 63);
    } else {
        float dt = (t_f - ts[i]) / (float)n_steps;
        integrate<0, false>(qx, qy, qz, px, py, pz, dt, n_steps - 1);
    }

    int orow = 2 * i + b;
    float2* __restrict__ orow_p = reinterpret_cast<float2*>(out + 6 * orow);
    orow_p[0] = make_float2(qx, qy);
    orow_p[1] = make_float2(qz, px);
    orow_p[2] = make_float2(py, pz);
}

extern "C" void kernel_launch(void* const* d_in, const int* in_sizes, int n_in,
                              void* d_out, int out_size) {
    const float* ts       = (const float*)d_in[0];
    const float* w0_lead  = (const float*)d_in[1];
    const float* w0_trail = (const float*)d_in[2];
    const int*   n_steps  = (const int*)d_in[3];
    float* out = (float*)d_out;

    int N = in_sizes[0];
    int total = 2 * N;
    int threads = 64;                   // 2048 CTAs -> balanced 13-14 per SM
    int blocks = (total + threads - 1) / threads;
    leapfrog_v12_kernel<<<blocks, threads>>>(ts, w0_lead, w0_trail, n_steps, out, N);
}

// round 15
// speedup vs baseline: 1.1830x; 1.0201x over previous
#include <cuda_runtime.h>

// Leapfrog (KDK), softened point mass: a = -q / (r*(r+1)^2 + 1e-12).
//
// v14 = v12 base (1 MUFU/step; g = 1/(1+r) loop-carried) with the dependency
// chain shortened SAFELY after v13's accuracy failure (1 Newton = e_seed^2 =
// 1.8e-3 FAIL; measured e_seed ~ 4e-2 worst-tail):
//  - s = fma(r2, u, 1)        exact, removes r=r2*u from the path
//  - extrapolated seed gp = 2g - g_old (off-path), clamped to [1/32, 1]
//  - HALLEY corrector (cubic, 3 FMA, 12cyc serial): e_after ~ e_seed^3 ~ 7e-5,
//    13x inside the 1e-3 budget, vs two Newtons' 16cyc.
// Chain ~72 -> ~60 cyc at one fewer slot than v12.
//
// Inputs: d_in[0]=ts f32[N], d_in[1]=w0_lead f32[N,6], d_in[2]=w0_trail f32[N,6],
//         d_in[3]=n_steps i32. Output f32[2N,6]: row 2i=trail_i, 2i+1=lead_i.

__device__ __forceinline__ float rsqrt_ap(float x) {
    float r; asm("rsqrt.approx.f32 %0, %1;" : "=f"(r) : "f"(x)); return r;
}

__device__ __forceinline__ void drift3(float& qx, float& qy, float& qz,
                                       float px, float py, float pz, float dt) {
    qx = fmaf(dt, px, qx);
    qy = fmaf(dt, py, qy);
    qz = fmaf(dt, pz, qz);
}

// Full-accuracy accel eval (2 MUFU), seeds g = 1/(1+r) and applies kick.
__device__ __forceinline__ void kick_init(float& qx, float& qy, float& qz,
                                          float& px, float& py, float& pz,
                                          float ncoef, float& g) {
    float r2 = fmaf(qx, qx, fmaf(qy, qy, qz * qz));
    float u  = rsqrt_ap(r2);             // 1/r
    float s  = fmaf(r2, u, 1.0f);        // 1 + r
    g        = rsqrt_ap(s * s);          // 1/(1+r)
    float sc = (ncoef * u) * (g * g);    // -coef/(r(1+r)^2)
    px = fmaf(sc, qx, px);
    py = fmaf(sc, qy, py);
    pz = fmaf(sc, qz, pz);
}

// Fast kick: 1 MUFU; g refreshed by one HALLEY step from an extrapolated seed.
__device__ __forceinline__ void kick_fast(float& qx, float& qy, float& qz,
                                          float& px, float& py, float& pz,
                                          float ncoef, float& g, float& g_old) {
    float r2 = fmaf(qx, qx, fmaf(qy, qy, qz * qz));
    float u  = rsqrt_ap(r2);             // only MUFU on the path
    float s  = fmaf(r2, u, 1.0f);        // 1 + r
    // Extrapolated seed (off-path inputs), clamped to the valid range of g.
    float gp = fmaf(2.0f, g, -g_old);
    gp = fminf(fmaxf(gp, 0.03125f), 1.0f);
    g_old = g;
    // Halley toward 1/s (cubic): h = 1 - s*gp; g = gp*(1 + h + h^2)
    float h  = fmaf(-s, gp, 1.0f);
    float hh = fmaf(h, h, h);            // h + h^2
    g  = fmaf(gp, hh, gp);
    float nu = ncoef * u;                // off the g-chain, overlaps Halley
    float sc = nu * (g * g);             // -coef/(r(1+r)^2)
    px = fmaf(sc, qx, px);
    py = fmaf(sc, qy, py);
    pz = fmaf(sc, qz, pz);
}

template <int INTERIOR, bool FULL_UNROLL>
__device__ __forceinline__ void integrate(float& qx, float& qy, float& qz,
                                          float& px, float& py, float& pz,
                                          float dt, int interior_rt) {
    float nhdt = -0.5f * dt;
    float ndt  = -dt;
    float g, g_old;

    kick_init(qx, qy, qz, px, py, pz, nhdt, g);
    g_old = g;                            // zero second-difference start

    if (FULL_UNROLL) {
        #pragma unroll
        for (int s = 0; s < INTERIOR; ++s) {
            drift3(qx, qy, qz, px, py, pz, dt);
            kick_fast(qx, qy, qz, px, py, pz, ndt, g, g_old);
        }
    } else {
        #pragma unroll 4
        for (int s = 0; s < interior_rt; ++s) {
            drift3(qx, qy, qz, px, py, pz, dt);
            kick_fast(qx, qy, qz, px, py, pz, ndt, g, g_old);
        }
    }
    drift3(qx, qy, qz, px, py, pz, dt);
    kick_fast(qx, qy, qz, px, py, pz, nhdt, g, g_old);
}

__global__ void __launch_bounds__(64)
leapfrog_v14_kernel(const float* __restrict__ ts,
                    const float* __restrict__ w0_lead,
                    const float* __restrict__ w0_trail,
                    const int*   __restrict__ n_steps_ptr,
                    float* __restrict__ out,
                    int N) {
    int tid = blockIdx.x * blockDim.x + threadIdx.x;
    if (tid >= 2 * N) return;

    int b = (tid >= N) ? 1 : 0;        // 0 = trail, 1 = lead
    int i = tid - b * N;

    const float* __restrict__ w0 = b ? w0_lead : w0_trail;

    int n_steps = *n_steps_ptr;
    float t_f = ts[N - 1] + 0.001f;    // broadcast, L2-resident

    const float2* __restrict__ row = reinterpret_cast<const float2*>(w0 + 6 * i);
    float2 v0 = row[0];
    float2 v1 = row[1];
    float2 v2 = row[2];
    float qx = v0.x, qy = v0.y, qz = v1.x;
    float px = v1.y, py = v2.x, pz = v2.y;

    if (n_steps == 64) {
        float dt = (t_f - ts[i]) * 0.015625f;   // exact /64
        integrate<63, true>(qx, qy, qz, px, py, pz, dt, 63);
    } else {
        float dt = (t_f - ts[i]) / (float)n_steps;
        integrate<0, false>(qx, qy, qz, px, py, pz, dt, n_steps - 1);
    }

    int orow = 2 * i + b;
    float2* __restrict__ orow_p = reinterpret_cast<float2*>(out + 6 * orow);
    orow_p[0] = make_float2(qx, qy);
    orow_p[1] = make_float2(qz, px);
    orow_p[2] = make_float2(py, pz);
}

extern "C" void kernel_launch(void* const* d_in, const int* in_sizes, int n_in,
                              void* d_out, int out_size) {
    const float* ts       = (const float*)d_in[0];
    const float* w0_lead  = (const float*)d_in[1];
    const float* w0_trail = (const float*)d_in[2];
    const int*   n_steps  = (const int*)d_in[3];
    float* out = (float*)d_out;

    int N = in_sizes[0];
    int total = 2 * N;
    int threads = 64;                   // 2048 CTAs -> balanced 13-14 per SM
    int blocks = (total + threads - 1) / threads;
    leapfrog_v14_kernel<<<blocks, threads>>>(ts, w0_lead, w0_trail, n_steps, out, N);
}